// round 13
// baseline (speedup 1.0000x reference)
#include <cuda_runtime.h>
#include <cuda_fp16.h>
#include <cuda_bf16.h>

// ---------------------------------------------------------------------------
// GNN: 4x GCNConv (3->16->32->48->64, relu) + global max pool + 2-layer MLP
// Round-13: launch_bounds reverted (was a small regression). Gather rewritten
// as unroll-4 predicated pair batches: 4 independent index loads + 8
// independent feature loads in flight (MLP 8) against ~240cyc L2 latency.
// ---------------------------------------------------------------------------

#define N_MAX 131072
#define E_MAX 3500000
#define G_MAX 512

__device__ int    g_deg[N_MAX];            // real in-degree (no self loop)
__device__ int    g_cursor[N_MAX];
__device__ int    g_off[N_MAX + 1];        // padded CSR offsets (all even)
__device__ __align__(16) int g_src[E_MAX]; // CSR: [self, real edges..., pad(n)]
__device__ int    g_bsum[256];
__device__ int    g_boff[256];
__device__ float  g_dinv[N_MAX];
__device__ uint2  g_s0[N_MAX + 1];          // layer-1 input half4, dinv-scaled (+dummy)
__device__ uint4  g_fA[(N_MAX + 1) * 8];    // feature buffer A
__device__ uint4  g_fB[(N_MAX + 1) * 8];    // feature buffer B
__device__ float  g_pool[G_MAX * 64];

// packed f32x2 accumulate of a half2 word: acc(2xf32) += cvt(2xf16)
__device__ __forceinline__ void acc_h2(unsigned long long& acc, __half2 h) {
    unsigned h2v = *reinterpret_cast<unsigned*>(&h);
    asm("{\n\t"
        ".reg .b16 h0, h1;\n\t"
        ".reg .f32 f0, f1;\n\t"
        ".reg .b64 t;\n\t"
        "mov.b32 {h0, h1}, %1;\n\t"
        "cvt.f32.f16 f0, h0;\n\t"
        "cvt.f32.f16 f1, h1;\n\t"
        "mov.b64 t, {f0, f1};\n\t"
        "add.rn.f32x2 %0, %0, t;\n\t"
        "}" : "+l"(acc) : "r"(h2v));
}
__device__ __forceinline__ void unpack2(unsigned long long a, float& lo, float& hi) {
    asm("mov.b64 {%0, %1}, %2;" : "=f"(lo), "=f"(hi) : "l"(a));
}
__device__ __forceinline__ __half2 u2h(unsigned u) { return *reinterpret_cast<__half2*>(&u); }

// ---------------------------- CSR construction ----------------------------

__global__ void init_kernel(int n, int gtot) {
    int i = blockIdx.x * blockDim.x + threadIdx.x;
    int tot = (n > gtot) ? n : gtot;
    for (; i < tot; i += gridDim.x * blockDim.x) {
        if (i < n) g_deg[i] = 0;
        if (i < gtot) g_pool[i] = 0.0f;   // relu outputs >= 0 -> 0 is max-identity
    }
    int t = blockIdx.x * blockDim.x + threadIdx.x;
    if (t < 8) {
        uint4 z; z.x = z.y = z.z = z.w = 0u;
        if (t == 0) { uint2 z2; z2.x = z2.y = 0u; g_s0[n] = z2; }
        if (t < 2)  g_fA[n * 2 + t] = z;    // fA as CIN=16 input (stride 2)
        g_fA[n * 8 + t] = z;                // fA as CIN=48 input (stride 8)
        if (t < 4)  g_fB[n * 4 + t] = z;    // fB as CIN=32 input (stride 4)
    }
}

__global__ void hist_kernel(const int* __restrict__ col, int e) {
    int i = blockIdx.x * blockDim.x + threadIdx.x;
    int e2 = e >> 1;
    if (i < e2) {
        int2 c = reinterpret_cast<const int2*>(col)[i];
        atomicAdd(&g_deg[c.x], 1);
        atomicAdd(&g_deg[c.y], 1);
    }
    if (i == 0 && (e & 1)) atomicAdd(&g_deg[col[e - 1]], 1);
}

// padded per-node slot count: self + real edges, rounded up to even
__device__ __forceinline__ int padded_cnt(int deg) { return (deg + 2) & ~1; }

// two-level exclusive scan of padded counts -> g_off
__global__ void scan_local(int n) {
    __shared__ int sm[256];
    int b = blockIdx.x, t = threadIdx.x;
    int i0 = b * 512 + 2 * t, i1 = i0 + 1;
    int v0 = (i0 < n) ? padded_cnt(g_deg[i0]) : 0;
    int v1 = (i1 < n) ? padded_cnt(g_deg[i1]) : 0;
    sm[t] = v0 + v1;
    __syncthreads();
    for (int o = 1; o < 256; o <<= 1) {
        int x = (t >= o) ? sm[t - o] : 0;
        __syncthreads();
        sm[t] += x;
        __syncthreads();
    }
    int ex = (t > 0) ? sm[t - 1] : 0;
    if (i0 < n) g_off[i0] = ex;
    if (i1 < n) g_off[i1] = ex + v0;
    if (t == 255) g_bsum[b] = sm[255];
}

__global__ void scan_spine(int nblk) {
    __shared__ int sm[256];
    int t = threadIdx.x;
    sm[t] = (t < nblk) ? g_bsum[t] : 0;
    __syncthreads();
    for (int o = 1; o < 256; o <<= 1) {
        int x = (t >= o) ? sm[t - o] : 0;
        __syncthreads();
        sm[t] += x;
        __syncthreads();
    }
    g_boff[t] = (t > 0) ? sm[t - 1] : 0;
}

// finalize offsets; self-loop entry + pad entry; seed cursors; dinv + s0 prep
__global__ void scan_add_dinv(const float* __restrict__ x, int n) {
    int i = blockIdx.x * blockDim.x + threadIdx.x;
    if (i < n) {
        int off = g_off[i] + g_boff[i >> 9];
        g_off[i] = off;
        g_cursor[i] = off + 1;            // slot 0 = self loop
        g_src[off] = i;                   // self
        int dp1 = g_deg[i] + 1;           // self + real edges
        if (dp1 & 1) g_src[off + dp1] = n;   // pad to even with dummy
        if (i == n - 1) g_off[n] = off + ((dp1 + 1) & ~1);
        float dv = rsqrtf((float)dp1);
        g_dinv[i] = dv;
        __half2 lo = __floats2half2_rn(dv * x[3*i],   dv * x[3*i+1]);
        __half2 hi = __floats2half2_rn(dv * x[3*i+2], 0.0f);
        uint2 w;
        w.x = *reinterpret_cast<unsigned*>(&lo);
        w.y = *reinterpret_cast<unsigned*>(&hi);
        g_s0[i] = w;
    }
}

__global__ void fill_kernel(const int* __restrict__ row, const int* __restrict__ col, int e) {
    int i = blockIdx.x * blockDim.x + threadIdx.x;
    int e2 = e >> 1;
    if (i < e2) {
        int2 c = reinterpret_cast<const int2*>(col)[i];
        int2 w = reinterpret_cast<const int2*>(row)[i];
        g_src[atomicAdd(&g_cursor[c.x], 1)] = w.x;
        g_src[atomicAdd(&g_cursor[c.y], 1)] = w.y;
    }
    if (i == 0 && (e & 1))
        g_src[atomicAdd(&g_cursor[col[e - 1]], 1)] = row[e - 1];
}

// ------------------------------- GCN layers -------------------------------

// Layer 1 (Cin=3 pad 4 -> Cout=16): edge pairs, pairwise hadd2 + fp32 acc.
__global__ void layer1_kernel(const float* __restrict__ W, const float* __restrict__ b, int n) {
    __shared__ float Ws[48];
    __shared__ float bs[16];
    if (threadIdx.x < 48) Ws[threadIdx.x] = W[threadIdx.x];
    if (threadIdx.x < 16) bs[threadIdx.x] = b[threadIdx.x];
    __syncthreads();
    int warp = threadIdx.x >> 5, lane = threadIdx.x & 31;
    int v = blockIdx.x * 8 + warp;
    if (v >= n) return;
    const int jbase = g_off[v];
    const int jend  = g_off[v + 1];
    unsigned long long A0 = 0ull, A1 = 0ull;
#pragma unroll 2
    for (int base = jbase + lane * 2; base < jend; base += 64) {
        int2 p = *reinterpret_cast<const int2*>(g_src + base);
        uint2 w0 = g_s0[p.x];
        uint2 w1 = g_s0[p.y];
        acc_h2(A0, __hadd2(u2h(w0.x), u2h(w1.x)));
        acc_h2(A1, __hadd2(u2h(w0.y), u2h(w1.y)));
    }
    float ax, ay, az, azw;
    unpack2(A0, ax, ay);
    unpack2(A1, az, azw);
#pragma unroll
    for (int o = 16; o; o >>= 1) {
        ax += __shfl_xor_sync(0xffffffffu, ax, o);
        ay += __shfl_xor_sync(0xffffffffu, ay, o);
        az += __shfl_xor_sync(0xffffffffu, az, o);
    }
    float dv = g_dinv[v];
    ax *= dv; ay *= dv; az *= dv;
    if (lane < 16) {
        float r = bs[lane] + ax * Ws[lane*3] + ay * Ws[lane*3+1] + az * Ws[lane*3+2];
        __half* outh = reinterpret_cast<__half*>(g_fA);
        outh[v * 16 + lane] = __float2half_rn(dv * fmaxf(r, 0.0f));  // pre-scale
    }
}

// Layers 2-4: unroll-4 predicated pair gather (8 feature loads in flight),
// pairwise hadd2 pre-accumulate, float4-vectorized smem matmul.
template <int CIN, int COUT, int IS4, int OS, bool SCALE>
__global__ void layer_kernel(const uint4* __restrict__ s, __half* __restrict__ outh,
                             const float* __restrict__ W, const float* __restrict__ b,
                             int n) {
    constexpr int QC  = CIN / 8;          // 2, 4, 6
    constexpr int EG  = 32 / QC;          // 16, 8, 5
    constexpr int ACT = QC * EG;          // 32, 32, 30
    constexpr int K4  = CIN / 4;          // float4 k-steps
    constexpr int WR  = CIN + 4;          // padded W row; WR/4 odd -> conflict-free
    __shared__ __align__(16) float Wcol[COUT * WR];   // channel-major weights
    __shared__ float bs[COUT];
    __shared__ float4 aggS4[8][K4];
    for (int i = threadIdx.x; i < CIN * COUT; i += blockDim.x) {
        int c = i / CIN, k = i - c * CIN;
        Wcol[c * WR + k] = W[i];
    }
    if (threadIdx.x < COUT) bs[threadIdx.x] = b[threadIdx.x];
    __syncthreads();
    int warp = threadIdx.x >> 5, lane = threadIdx.x & 31;
    int v = blockIdx.x * 8 + warp;
    if (v >= n) return;
    const float dv = g_dinv[v];
    const int eg = lane / QC;
    const int q  = lane - eg * QC;
    const bool active = (ACT == 32) || (lane < ACT);

    const int jbase = g_off[v];
    const int P = (g_off[v + 1] - jbase) >> 1;      // pair count (rows even)
    const int2* ps = reinterpret_cast<const int2*>(g_src + jbase);

    unsigned long long A0 = 0ull, A1 = 0ull, A2 = 0ull, A3 = 0ull;
    const int nB = (P + 4 * EG - 1) / (4 * EG);     // warp-uniform batches
    for (int bb = 0; bb < nB; bb++) {
        const int t0 = eg + bb * (4 * EG);
        int2 p[4];
#pragma unroll
        for (int k = 0; k < 4; k++) {
            int t = t0 + k * EG;
            p[k] = (active && t < P) ? ps[t] : make_int2(n, n);
        }
        uint4 wa[4], wb[4];
#pragma unroll
        for (int k = 0; k < 4; k++) {
            wa[k] = s[p[k].x * IS4 + q];
            wb[k] = s[p[k].y * IS4 + q];
        }
#pragma unroll
        for (int k = 0; k < 4; k++) {
            acc_h2(A0, __hadd2(u2h(wa[k].x), u2h(wb[k].x)));   // one fp16 add per
            acc_h2(A1, __hadd2(u2h(wa[k].y), u2h(wb[k].y)));   // element, then
            acc_h2(A2, __hadd2(u2h(wa[k].z), u2h(wb[k].z)));   // exact fp32 acc
            acc_h2(A3, __hadd2(u2h(wa[k].w), u2h(wb[k].w)));
        }
    }
    float f[8];
    unpack2(A0, f[0], f[1]);
    unpack2(A1, f[2], f[3]);
    unpack2(A2, f[4], f[5]);
    unpack2(A3, f[6], f[7]);
    // reduce across edge groups (fp32, exact lane bookkeeping)
    if constexpr (QC == 2 || QC == 4) {
#pragma unroll
        for (int o = QC; o < 32; o <<= 1)
#pragma unroll
            for (int j = 0; j < 8; j++) f[j] += __shfl_xor_sync(0xffffffffu, f[j], o);
    } else {   // QC == 6: groups at lanes q + {0,6,12,18,24}; guarded 3-step sum
#pragma unroll
        for (int j = 0; j < 8; j++) {
            float t = __shfl_down_sync(0xffffffffu, f[j], 18);
            if (lane < 12) f[j] += t;           // q += q+18 ; q+6 += q+24
        }
#pragma unroll
        for (int j = 0; j < 8; j++) {
            float t = __shfl_down_sync(0xffffffffu, f[j], 6);
            if (lane < 6) f[j] += t;            // q += (q+6 + q+24)
        }
#pragma unroll
        for (int j = 0; j < 8; j++) {
            float t = __shfl_down_sync(0xffffffffu, f[j], 12);
            if (lane < 6) f[j] += t;            // q += q+12
        }
    }
    if (lane < QC) {   // two STS.128 per reducing lane
        aggS4[warp][lane * 2]     = make_float4(f[0]*dv, f[1]*dv, f[2]*dv, f[3]*dv);
        aggS4[warp][lane * 2 + 1] = make_float4(f[4]*dv, f[5]*dv, f[6]*dv, f[7]*dv);
    }
    __syncwarp();
    float r0 = bs[lane];
    float r1 = (COUT > 32 && lane + 32 < COUT) ? bs[lane + 32] : 0.0f;
    const float4* w4a = reinterpret_cast<const float4*>(&Wcol[lane * WR]);
    const float4* w4b = (COUT > 32 && lane + 32 < COUT)
                        ? reinterpret_cast<const float4*>(&Wcol[(lane + 32) * WR]) : w4a;
#pragma unroll
    for (int k4 = 0; k4 < K4; k4++) {
        float4 a  = aggS4[warp][k4];       // LDS.128 broadcast
        float4 wa = w4a[k4];               // LDS.128, conflict-free (WR/4 odd)
        r0 += a.x * wa.x + a.y * wa.y + a.z * wa.z + a.w * wa.w;
        if (COUT > 32 && lane + 32 < COUT) {
            float4 wb = w4b[k4];
            r1 += a.x * wb.x + a.y * wb.y + a.z * wb.z + a.w * wb.w;
        }
    }
    r0 = fmaxf(r0, 0.0f);
    if (SCALE) r0 *= dv;
    outh[v * OS + lane] = __float2half_rn(r0);
    if (COUT > 32 && lane + 32 < COUT) {
        r1 = fmaxf(r1, 0.0f);
        if (SCALE) r1 *= dv;
        outh[v * OS + lane + 32] = __float2half_rn(r1);
    }
}

// --------------------------- pool + final MLP ------------------------------

__device__ __forceinline__ void pool_flush(int cur, int c, __half2 m) {
    float2 f = __half22float2(m);
    atomicMax((int*)&g_pool[cur * 64 + 2 * c],     __float_as_int(f.x));
    atomicMax((int*)&g_pool[cur * 64 + 2 * c + 1], __float_as_int(f.y));
}

__global__ void pool_kernel(const __half2* __restrict__ h2, const int* __restrict__ batch, int n) {
    const int NPB = 256;
    int c = threadIdx.x;   // 32 threads = 32 half2 channel pairs
    int start = blockIdx.x * NPB;
    if (start >= n) return;
    int end = start + NPB; if (end > n) end = n;
    int cur = batch[start];
    __half2 m = __float2half2_rn(0.0f);
    for (int v = start; v < end; v++) {
        int gi = batch[v];
        if (gi != cur) {
            pool_flush(cur, c, m);
            cur = gi;
            m = __float2half2_rn(0.0f);
        }
        m = __hmax2(m, h2[v * 32 + c]);
    }
    pool_flush(cur, c, m);
}

__global__ void mlp_kernel(const float* __restrict__ L1w, const float* __restrict__ L1b,
                           const float* __restrict__ L2w, const float* __restrict__ L2b,
                           float* __restrict__ out) {
    __shared__ float gs[64];
    __shared__ float t1[64];
    int gi = blockIdx.x;
    int t = threadIdx.x;   // 64 threads
    gs[t] = g_pool[gi * 64 + t];
    __syncthreads();
    float acc = L1b[t];
#pragma unroll
    for (int k = 0; k < 64; k++) acc += gs[k] * L1w[t * 64 + k];
    t1[t] = fmaxf(acc, 0.0f);
    __syncthreads();
    if (t < 10) {
        float a = L2b[t];
#pragma unroll
        for (int k = 0; k < 64; k++) a += t1[k] * L2w[t * 64 + k];
        out[gi * 10 + t] = a;
    }
}

// ------------------------------- launcher ----------------------------------

extern "C" void kernel_launch(void* const* d_in, const int* in_sizes, int n_in,
                              void* d_out, int out_size) {
    const float* x     = (const float*)d_in[0];
    const int*   ei    = (const int*)d_in[1];
    const int*   batch = (const int*)d_in[2];
    const float* W1 = (const float*)d_in[4];
    const float* b1 = (const float*)d_in[5];
    const float* W2 = (const float*)d_in[6];
    const float* b2 = (const float*)d_in[7];
    const float* W3 = (const float*)d_in[8];
    const float* b3 = (const float*)d_in[9];
    const float* W4 = (const float*)d_in[10];
    const float* b4 = (const float*)d_in[11];
    const float* L1w = (const float*)d_in[12];
    const float* L1b = (const float*)d_in[13];
    const float* L2w = (const float*)d_in[14];
    const float* L2b = (const float*)d_in[15];
    float* out = (float*)d_out;

    const int n = in_sizes[0] / 3;
    const int e = in_sizes[1] / 2;
    const int G = out_size / 10;

    const int* row = ei;
    const int* col = ei + e;

    uint4* fA; cudaGetSymbolAddress((void**)&fA, g_fA);
    uint4* fB; cudaGetSymbolAddress((void**)&fB, g_fB);

    // ---- CSR build + prep ----
    {
        int tot = (n > G * 64) ? n : G * 64;
        init_kernel<<<(tot + 255) / 256, 256>>>(n, G * 64);
        hist_kernel<<<((e >> 1) + 255) / 256, 256>>>(col, e);
        int nblk = (n + 511) / 512;
        scan_local<<<nblk, 256>>>(n);
        scan_spine<<<1, 256>>>(nblk);
        scan_add_dinv<<<(n + 255) / 256, 256>>>(x, n);
        fill_kernel<<<((e >> 1) + 255) / 256, 256>>>(row, col, e);
    }

    const int agg_grid = (n + 7) / 8;   // 8 warps/block, warp per node

    // ---- fused layers: gather(Cin, fp16) -> W -> relu -> (dinv-prescale) ----
    layer1_kernel<<<agg_grid, 256>>>(W1, b1, n);                                  // 3->16 -> fA (stride 2)
    layer_kernel<16, 32, 2, 32, true ><<<agg_grid, 256>>>(fA, (__half*)fB, W2, b2, n); // 16->32 -> fB (stride 4)
    layer_kernel<32, 48, 4, 64, true ><<<agg_grid, 256>>>(fB, (__half*)fA, W3, b3, n); // 32->48 -> fA (stride 8)
    layer_kernel<48, 64, 8, 64, false><<<agg_grid, 256>>>(fA, (__half*)fB, W4, b4, n); // 48->64 -> fB

    // ---- pool + MLP ----
    pool_kernel<<<(n + 255) / 256, 32>>>((const __half2*)fB, batch, n);
    mlp_kernel<<<G, 64>>>(L1w, L1b, L2w, L2b, out);
}

// round 14
// speedup vs baseline: 1.0640x; 1.0640x over previous
#include <cuda_runtime.h>
#include <cuda_fp16.h>
#include <cuda_bf16.h>

// ---------------------------------------------------------------------------
// GNN: 4x GCNConv (3->16->32->48->64, relu) + global max pool + 2-layer MLP
// Round-14: lock in best-known config = r12 minus __launch_bounds__ (its
// decomposed ~5us penalty). Simple pair-walk gather (r11 structure), pairwise
// hadd2 + packed f32x2 accumulate, float4 smem matmul. No decoy.
// ---------------------------------------------------------------------------

#define N_MAX 131072
#define E_MAX 3500000
#define G_MAX 512

__device__ int    g_deg[N_MAX];            // real in-degree (no self loop)
__device__ int    g_cursor[N_MAX];
__device__ int    g_off[N_MAX + 1];        // padded CSR offsets (all even)
__device__ __align__(16) int g_src[E_MAX]; // CSR: [self, real edges..., pad(n)]
__device__ int    g_bsum[256];
__device__ int    g_boff[256];
__device__ float  g_dinv[N_MAX];
__device__ uint2  g_s0[N_MAX + 1];          // layer-1 input half4, dinv-scaled (+dummy)
__device__ uint4  g_fA[(N_MAX + 1) * 8];    // feature buffer A
__device__ uint4  g_fB[(N_MAX + 1) * 8];    // feature buffer B
__device__ float  g_pool[G_MAX * 64];

// packed f32x2 accumulate of a half2 word: acc(2xf32) += cvt(2xf16)
__device__ __forceinline__ void acc_h2(unsigned long long& acc, __half2 h) {
    unsigned h2v = *reinterpret_cast<unsigned*>(&h);
    asm("{\n\t"
        ".reg .b16 h0, h1;\n\t"
        ".reg .f32 f0, f1;\n\t"
        ".reg .b64 t;\n\t"
        "mov.b32 {h0, h1}, %1;\n\t"
        "cvt.f32.f16 f0, h0;\n\t"
        "cvt.f32.f16 f1, h1;\n\t"
        "mov.b64 t, {f0, f1};\n\t"
        "add.rn.f32x2 %0, %0, t;\n\t"
        "}" : "+l"(acc) : "r"(h2v));
}
__device__ __forceinline__ void unpack2(unsigned long long a, float& lo, float& hi) {
    asm("mov.b64 {%0, %1}, %2;" : "=f"(lo), "=f"(hi) : "l"(a));
}
__device__ __forceinline__ __half2 u2h(unsigned u) { return *reinterpret_cast<__half2*>(&u); }

// ---------------------------- CSR construction ----------------------------

__global__ void init_kernel(int n, int gtot) {
    int i = blockIdx.x * blockDim.x + threadIdx.x;
    int tot = (n > gtot) ? n : gtot;
    for (; i < tot; i += gridDim.x * blockDim.x) {
        if (i < n) g_deg[i] = 0;
        if (i < gtot) g_pool[i] = 0.0f;   // relu outputs >= 0 -> 0 is max-identity
    }
    int t = blockIdx.x * blockDim.x + threadIdx.x;
    if (t < 8) {
        uint4 z; z.x = z.y = z.z = z.w = 0u;
        if (t == 0) { uint2 z2; z2.x = z2.y = 0u; g_s0[n] = z2; }
        if (t < 2)  g_fA[n * 2 + t] = z;    // fA as CIN=16 input (stride 2)
        g_fA[n * 8 + t] = z;                // fA as CIN=48 input (stride 8)
        if (t < 4)  g_fB[n * 4 + t] = z;    // fB as CIN=32 input (stride 4)
    }
}

__global__ void hist_kernel(const int* __restrict__ col, int e) {
    int i = blockIdx.x * blockDim.x + threadIdx.x;
    int e2 = e >> 1;
    if (i < e2) {
        int2 c = reinterpret_cast<const int2*>(col)[i];
        atomicAdd(&g_deg[c.x], 1);
        atomicAdd(&g_deg[c.y], 1);
    }
    if (i == 0 && (e & 1)) atomicAdd(&g_deg[col[e - 1]], 1);
}

// padded per-node slot count: self + real edges, rounded up to even
__device__ __forceinline__ int padded_cnt(int deg) { return (deg + 2) & ~1; }

// two-level exclusive scan of padded counts -> g_off
__global__ void scan_local(int n) {
    __shared__ int sm[256];
    int b = blockIdx.x, t = threadIdx.x;
    int i0 = b * 512 + 2 * t, i1 = i0 + 1;
    int v0 = (i0 < n) ? padded_cnt(g_deg[i0]) : 0;
    int v1 = (i1 < n) ? padded_cnt(g_deg[i1]) : 0;
    sm[t] = v0 + v1;
    __syncthreads();
    for (int o = 1; o < 256; o <<= 1) {
        int x = (t >= o) ? sm[t - o] : 0;
        __syncthreads();
        sm[t] += x;
        __syncthreads();
    }
    int ex = (t > 0) ? sm[t - 1] : 0;
    if (i0 < n) g_off[i0] = ex;
    if (i1 < n) g_off[i1] = ex + v0;
    if (t == 255) g_bsum[b] = sm[255];
}

__global__ void scan_spine(int nblk) {
    __shared__ int sm[256];
    int t = threadIdx.x;
    sm[t] = (t < nblk) ? g_bsum[t] : 0;
    __syncthreads();
    for (int o = 1; o < 256; o <<= 1) {
        int x = (t >= o) ? sm[t - o] : 0;
        __syncthreads();
        sm[t] += x;
        __syncthreads();
    }
    g_boff[t] = (t > 0) ? sm[t - 1] : 0;
}

// finalize offsets; self-loop entry + pad entry; seed cursors; dinv + s0 prep
__global__ void scan_add_dinv(const float* __restrict__ x, int n) {
    int i = blockIdx.x * blockDim.x + threadIdx.x;
    if (i < n) {
        int off = g_off[i] + g_boff[i >> 9];
        g_off[i] = off;
        g_cursor[i] = off + 1;            // slot 0 = self loop
        g_src[off] = i;                   // self
        int dp1 = g_deg[i] + 1;           // self + real edges
        if (dp1 & 1) g_src[off + dp1] = n;   // pad to even with dummy
        if (i == n - 1) g_off[n] = off + ((dp1 + 1) & ~1);
        float dv = rsqrtf((float)dp1);
        g_dinv[i] = dv;
        __half2 lo = __floats2half2_rn(dv * x[3*i],   dv * x[3*i+1]);
        __half2 hi = __floats2half2_rn(dv * x[3*i+2], 0.0f);
        uint2 w;
        w.x = *reinterpret_cast<unsigned*>(&lo);
        w.y = *reinterpret_cast<unsigned*>(&hi);
        g_s0[i] = w;
    }
}

__global__ void fill_kernel(const int* __restrict__ row, const int* __restrict__ col, int e) {
    int i = blockIdx.x * blockDim.x + threadIdx.x;
    int e2 = e >> 1;
    if (i < e2) {
        int2 c = reinterpret_cast<const int2*>(col)[i];
        int2 w = reinterpret_cast<const int2*>(row)[i];
        g_src[atomicAdd(&g_cursor[c.x], 1)] = w.x;
        g_src[atomicAdd(&g_cursor[c.y], 1)] = w.y;
    }
    if (i == 0 && (e & 1))
        g_src[atomicAdd(&g_cursor[col[e - 1]], 1)] = row[e - 1];
}

// ------------------------------- GCN layers -------------------------------

// Layer 1 (Cin=3 pad 4 -> Cout=16): edge pairs, pairwise hadd2 + fp32 acc.
__global__ void layer1_kernel(const float* __restrict__ W, const float* __restrict__ b, int n) {
    __shared__ float Ws[48];
    __shared__ float bs[16];
    if (threadIdx.x < 48) Ws[threadIdx.x] = W[threadIdx.x];
    if (threadIdx.x < 16) bs[threadIdx.x] = b[threadIdx.x];
    __syncthreads();
    int warp = threadIdx.x >> 5, lane = threadIdx.x & 31;
    int v = blockIdx.x * 8 + warp;
    if (v >= n) return;
    const int jbase = g_off[v];
    const int jend  = g_off[v + 1];
    unsigned long long A0 = 0ull, A1 = 0ull;
#pragma unroll 2
    for (int base = jbase + lane * 2; base < jend; base += 64) {
        int2 p = *reinterpret_cast<const int2*>(g_src + base);
        uint2 w0 = g_s0[p.x];
        uint2 w1 = g_s0[p.y];
        acc_h2(A0, __hadd2(u2h(w0.x), u2h(w1.x)));
        acc_h2(A1, __hadd2(u2h(w0.y), u2h(w1.y)));
    }
    float ax, ay, az, azw;
    unpack2(A0, ax, ay);
    unpack2(A1, az, azw);
#pragma unroll
    for (int o = 16; o; o >>= 1) {
        ax += __shfl_xor_sync(0xffffffffu, ax, o);
        ay += __shfl_xor_sync(0xffffffffu, ay, o);
        az += __shfl_xor_sync(0xffffffffu, az, o);
    }
    float dv = g_dinv[v];
    ax *= dv; ay *= dv; az *= dv;
    if (lane < 16) {
        float r = bs[lane] + ax * Ws[lane*3] + ay * Ws[lane*3+1] + az * Ws[lane*3+2];
        __half* outh = reinterpret_cast<__half*>(g_fA);
        outh[v * 16 + lane] = __float2half_rn(dv * fmaxf(r, 0.0f));  // pre-scale
    }
}

// Layers 2-4: uint4 gathers in edge pairs, pairwise hadd2 pre-accumulate,
// float4-vectorized smem matmul.
template <int CIN, int COUT, int IS4, int OS, bool SCALE>
__global__ void layer_kernel(const uint4* __restrict__ s, __half* __restrict__ outh,
                             const float* __restrict__ W, const float* __restrict__ b,
                             int n) {
    constexpr int QC  = CIN / 8;          // 2, 4, 6
    constexpr int EG  = 32 / QC;          // 16, 8, 5
    constexpr int ACT = QC * EG;          // 32, 32, 30
    constexpr int K4  = CIN / 4;          // float4 k-steps
    constexpr int WR  = CIN + 4;          // padded W row; WR/4 odd -> conflict-free
    __shared__ __align__(16) float Wcol[COUT * WR];   // channel-major weights
    __shared__ float bs[COUT];
    __shared__ float4 aggS4[8][K4];
    for (int i = threadIdx.x; i < CIN * COUT; i += blockDim.x) {
        int c = i / CIN, k = i - c * CIN;
        Wcol[c * WR + k] = W[i];
    }
    if (threadIdx.x < COUT) bs[threadIdx.x] = b[threadIdx.x];
    __syncthreads();
    int warp = threadIdx.x >> 5, lane = threadIdx.x & 31;
    int v = blockIdx.x * 8 + warp;
    if (v >= n) return;
    const float dv = g_dinv[v];
    const int eg = lane / QC;
    const int q  = lane - eg * QC;
    const bool active = (ACT == 32) || (lane < ACT);

    const int jbase = g_off[v];
    const int jend  = g_off[v + 1];

    unsigned long long A0 = 0ull, A1 = 0ull, A2 = 0ull, A3 = 0ull;
#pragma unroll 2
    for (int base = active ? (jbase + eg * 2) : jend; base < jend; base += 2 * EG) {
        int2 p = *reinterpret_cast<const int2*>(g_src + base);
        uint4 w0 = s[p.x * IS4 + q];
        uint4 w1 = s[p.y * IS4 + q];
        acc_h2(A0, __hadd2(u2h(w0.x), u2h(w1.x)));   // one fp16 add per element,
        acc_h2(A1, __hadd2(u2h(w0.y), u2h(w1.y)));   // then exact fp32 accumulate
        acc_h2(A2, __hadd2(u2h(w0.z), u2h(w1.z)));
        acc_h2(A3, __hadd2(u2h(w0.w), u2h(w1.w)));
    }
    float f[8];
    unpack2(A0, f[0], f[1]);
    unpack2(A1, f[2], f[3]);
    unpack2(A2, f[4], f[5]);
    unpack2(A3, f[6], f[7]);
    // reduce across edge groups (fp32, exact lane bookkeeping)
    if constexpr (QC == 2 || QC == 4) {
#pragma unroll
        for (int o = QC; o < 32; o <<= 1)
#pragma unroll
            for (int j = 0; j < 8; j++) f[j] += __shfl_xor_sync(0xffffffffu, f[j], o);
    } else {   // QC == 6: groups at lanes q + {0,6,12,18,24}; guarded 3-step sum
#pragma unroll
        for (int j = 0; j < 8; j++) {
            float t = __shfl_down_sync(0xffffffffu, f[j], 18);
            if (lane < 12) f[j] += t;           // q += q+18 ; q+6 += q+24
        }
#pragma unroll
        for (int j = 0; j < 8; j++) {
            float t = __shfl_down_sync(0xffffffffu, f[j], 6);
            if (lane < 6) f[j] += t;            // q += (q+6 + q+24)
        }
#pragma unroll
        for (int j = 0; j < 8; j++) {
            float t = __shfl_down_sync(0xffffffffu, f[j], 12);
            if (lane < 6) f[j] += t;            // q += q+12
        }
    }
    if (lane < QC) {   // two STS.128 per reducing lane
        aggS4[warp][lane * 2]     = make_float4(f[0]*dv, f[1]*dv, f[2]*dv, f[3]*dv);
        aggS4[warp][lane * 2 + 1] = make_float4(f[4]*dv, f[5]*dv, f[6]*dv, f[7]*dv);
    }
    __syncwarp();
    float r0 = bs[lane];
    float r1 = (COUT > 32 && lane + 32 < COUT) ? bs[lane + 32] : 0.0f;
    const float4* w4a = reinterpret_cast<const float4*>(&Wcol[lane * WR]);
    const float4* w4b = (COUT > 32 && lane + 32 < COUT)
                        ? reinterpret_cast<const float4*>(&Wcol[(lane + 32) * WR]) : w4a;
#pragma unroll
    for (int k4 = 0; k4 < K4; k4++) {
        float4 a  = aggS4[warp][k4];       // LDS.128 broadcast
        float4 wa = w4a[k4];               // LDS.128, conflict-free (WR/4 odd)
        r0 += a.x * wa.x + a.y * wa.y + a.z * wa.z + a.w * wa.w;
        if (COUT > 32 && lane + 32 < COUT) {
            float4 wb = w4b[k4];
            r1 += a.x * wb.x + a.y * wb.y + a.z * wb.z + a.w * wb.w;
        }
    }
    r0 = fmaxf(r0, 0.0f);
    if (SCALE) r0 *= dv;
    outh[v * OS + lane] = __float2half_rn(r0);
    if (COUT > 32 && lane + 32 < COUT) {
        r1 = fmaxf(r1, 0.0f);
        if (SCALE) r1 *= dv;
        outh[v * OS + lane + 32] = __float2half_rn(r1);
    }
}

// --------------------------- pool + final MLP ------------------------------

__device__ __forceinline__ void pool_flush(int cur, int c, __half2 m) {
    float2 f = __half22float2(m);
    atomicMax((int*)&g_pool[cur * 64 + 2 * c],     __float_as_int(f.x));
    atomicMax((int*)&g_pool[cur * 64 + 2 * c + 1], __float_as_int(f.y));
}

__global__ void pool_kernel(const __half2* __restrict__ h2, const int* __restrict__ batch, int n) {
    const int NPB = 256;
    int c = threadIdx.x;   // 32 threads = 32 half2 channel pairs
    int start = blockIdx.x * NPB;
    if (start >= n) return;
    int end = start + NPB; if (end > n) end = n;
    int cur = batch[start];
    __half2 m = __float2half2_rn(0.0f);
    for (int v = start; v < end; v++) {
        int gi = batch[v];
        if (gi != cur) {
            pool_flush(cur, c, m);
            cur = gi;
            m = __float2half2_rn(0.0f);
        }
        m = __hmax2(m, h2[v * 32 + c]);
    }
    pool_flush(cur, c, m);
}

__global__ void mlp_kernel(const float* __restrict__ L1w, const float* __restrict__ L1b,
                           const float* __restrict__ L2w, const float* __restrict__ L2b,
                           float* __restrict__ out) {
    __shared__ float gs[64];
    __shared__ float t1[64];
    int gi = blockIdx.x;
    int t = threadIdx.x;   // 64 threads
    gs[t] = g_pool[gi * 64 + t];
    __syncthreads();
    float acc = L1b[t];
#pragma unroll
    for (int k = 0; k < 64; k++) acc += gs[k] * L1w[t * 64 + k];
    t1[t] = fmaxf(acc, 0.0f);
    __syncthreads();
    if (t < 10) {
        float a = L2b[t];
#pragma unroll
        for (int k = 0; k < 64; k++) a += t1[k] * L2w[t * 64 + k];
        out[gi * 10 + t] = a;
    }
}

// ------------------------------- launcher ----------------------------------

extern "C" void kernel_launch(void* const* d_in, const int* in_sizes, int n_in,
                              void* d_out, int out_size) {
    const float* x     = (const float*)d_in[0];
    const int*   ei    = (const int*)d_in[1];
    const int*   batch = (const int*)d_in[2];
    const float* W1 = (const float*)d_in[4];
    const float* b1 = (const float*)d_in[5];
    const float* W2 = (const float*)d_in[6];
    const float* b2 = (const float*)d_in[7];
    const float* W3 = (const float*)d_in[8];
    const float* b3 = (const float*)d_in[9];
    const float* W4 = (const float*)d_in[10];
    const float* b4 = (const float*)d_in[11];
    const float* L1w = (const float*)d_in[12];
    const float* L1b = (const float*)d_in[13];
    const float* L2w = (const float*)d_in[14];
    const float* L2b = (const float*)d_in[15];
    float* out = (float*)d_out;

    const int n = in_sizes[0] / 3;
    const int e = in_sizes[1] / 2;
    const int G = out_size / 10;

    const int* row = ei;
    const int* col = ei + e;

    uint4* fA; cudaGetSymbolAddress((void**)&fA, g_fA);
    uint4* fB; cudaGetSymbolAddress((void**)&fB, g_fB);

    // ---- CSR build + prep ----
    {
        int tot = (n > G * 64) ? n : G * 64;
        init_kernel<<<(tot + 255) / 256, 256>>>(n, G * 64);
        hist_kernel<<<((e >> 1) + 255) / 256, 256>>>(col, e);
        int nblk = (n + 511) / 512;
        scan_local<<<nblk, 256>>>(n);
        scan_spine<<<1, 256>>>(nblk);
        scan_add_dinv<<<(n + 255) / 256, 256>>>(x, n);
        fill_kernel<<<((e >> 1) + 255) / 256, 256>>>(row, col, e);
    }

    const int agg_grid = (n + 7) / 8;   // 8 warps/block, warp per node

    // ---- fused layers: gather(Cin, fp16) -> W -> relu -> (dinv-prescale) ----
    layer1_kernel<<<agg_grid, 256>>>(W1, b1, n);                                  // 3->16 -> fA (stride 2)
    layer_kernel<16, 32, 2, 32, true ><<<agg_grid, 256>>>(fA, (__half*)fB, W2, b2, n); // 16->32 -> fB (stride 4)
    layer_kernel<32, 48, 4, 64, true ><<<agg_grid, 256>>>(fB, (__half*)fA, W3, b3, n); // 32->48 -> fA (stride 8)
    layer_kernel<48, 64, 8, 64, false><<<agg_grid, 256>>>(fA, (__half*)fB, W4, b4, n); // 48->64 -> fB

    // ---- pool + MLP ----
    pool_kernel<<<(n + 255) / 256, 32>>>((const __half2*)fB, batch, n);
    mlp_kernel<<<G, 64>>>(L1w, L1b, L2w, L2b, out);
}

// round 15
// speedup vs baseline: 1.1883x; 1.1169x over previous
#include <cuda_runtime.h>
#include <cuda_fp16.h>
#include <cuda_bf16.h>

// ---------------------------------------------------------------------------
// GNN: 4x GCNConv (3->16->32->48->64, relu) + global max pool + 2-layer MLP
// Round-15: cut fixed launch overhead (13 -> 11 kernels): init folded into
// fill's tail (deg/pool/dummy zeroing for NEXT replay), spine folded into
// scan_add_dinv (each block re-scans 196 block sums). Pool: 8 warps/block.
// Layer kernels frozen at r14 config (structural floor).
// ---------------------------------------------------------------------------

#define N_MAX 131072
#define E_MAX 3500000
#define G_MAX 512

__device__ int    g_deg[N_MAX];            // real in-degree (no self loop); zeroed by fill tail
__device__ int    g_cursor[N_MAX];
__device__ int    g_off[N_MAX + 1];        // padded CSR offsets (all even)
__device__ __align__(16) int g_src[E_MAX]; // CSR: [self, real edges..., pad(n)]
__device__ int    g_bsum[256];
__device__ float  g_dinv[N_MAX];
__device__ uint2  g_s0[N_MAX + 1];          // layer-1 input half4, dinv-scaled (+dummy)
__device__ uint4  g_fA[(N_MAX + 1) * 8];    // feature buffer A
__device__ uint4  g_fB[(N_MAX + 1) * 8];    // feature buffer B
__device__ float  g_pool[G_MAX * 64];       // zeroed by fill tail

// packed f32x2 accumulate of a half2 word: acc(2xf32) += cvt(2xf16)
__device__ __forceinline__ void acc_h2(unsigned long long& acc, __half2 h) {
    unsigned h2v = *reinterpret_cast<unsigned*>(&h);
    asm("{\n\t"
        ".reg .b16 h0, h1;\n\t"
        ".reg .f32 f0, f1;\n\t"
        ".reg .b64 t;\n\t"
        "mov.b32 {h0, h1}, %1;\n\t"
        "cvt.f32.f16 f0, h0;\n\t"
        "cvt.f32.f16 f1, h1;\n\t"
        "mov.b64 t, {f0, f1};\n\t"
        "add.rn.f32x2 %0, %0, t;\n\t"
        "}" : "+l"(acc) : "r"(h2v));
}
__device__ __forceinline__ void unpack2(unsigned long long a, float& lo, float& hi) {
    asm("mov.b64 {%0, %1}, %2;" : "=f"(lo), "=f"(hi) : "l"(a));
}
__device__ __forceinline__ __half2 u2h(unsigned u) { return *reinterpret_cast<__half2*>(&u); }

// ---------------------------- CSR construction ----------------------------
// NOTE: g_deg and g_pool must be ZERO at entry of each kernel_launch call.
// First call: CUDA zero-initializes __device__ globals. Subsequent calls:
// fill_kernel's tail re-zeroes them (it runs after their last consumer).

__global__ void hist_kernel(const int* __restrict__ col, int e) {
    int i = blockIdx.x * blockDim.x + threadIdx.x;
    int e2 = e >> 1;
    if (i < e2) {
        int2 c = reinterpret_cast<const int2*>(col)[i];
        atomicAdd(&g_deg[c.x], 1);
        atomicAdd(&g_deg[c.y], 1);
    }
    if (i == 0 && (e & 1)) atomicAdd(&g_deg[col[e - 1]], 1);
}

// padded per-node slot count: self + real edges, rounded up to even
__device__ __forceinline__ int padded_cnt(int deg) { return (deg + 2) & ~1; }

// block-local exclusive scan of padded counts -> g_off (local) + g_bsum
__global__ void scan_local(int n) {
    __shared__ int sm[256];
    int b = blockIdx.x, t = threadIdx.x;
    int i0 = b * 512 + 2 * t, i1 = i0 + 1;
    int v0 = (i0 < n) ? padded_cnt(g_deg[i0]) : 0;
    int v1 = (i1 < n) ? padded_cnt(g_deg[i1]) : 0;
    sm[t] = v0 + v1;
    __syncthreads();
    for (int o = 1; o < 256; o <<= 1) {
        int x = (t >= o) ? sm[t - o] : 0;
        __syncthreads();
        sm[t] += x;
        __syncthreads();
    }
    int ex = (t > 0) ? sm[t - 1] : 0;
    if (i0 < n) g_off[i0] = ex;
    if (i1 < n) g_off[i1] = ex + v0;
    if (t == 255) g_bsum[b] = sm[255];
}

// finalize offsets (each block re-scans the spine itself); self-loop entry +
// pad entry; seed cursors; dinv + s0 prep. Replaces scan_spine + scan_add.
__global__ void scan_add_dinv(const float* __restrict__ x, int n, int nblk) {
    __shared__ int sp[256];
    int t = threadIdx.x;
    sp[t] = (t < nblk) ? g_bsum[t] : 0;
    __syncthreads();
    for (int o = 1; o < 256; o <<= 1) {
        int v = (t >= o) ? sp[t - o] : 0;
        __syncthreads();
        sp[t] += v;
        __syncthreads();
    }
    int i = blockIdx.x * blockDim.x + t;
    if (i < n) {
        int chunk = i >> 9;
        int off = g_off[i] + ((chunk > 0) ? sp[chunk - 1] : 0);
        g_off[i] = off;
        g_cursor[i] = off + 1;            // slot 0 = self loop
        g_src[off] = i;                   // self
        int dp1 = g_deg[i] + 1;           // self + real edges
        if (dp1 & 1) g_src[off + dp1] = n;   // pad to even with dummy
        if (i == n - 1) g_off[n] = off + ((dp1 + 1) & ~1);
        float dv = rsqrtf((float)dp1);
        g_dinv[i] = dv;
        __half2 lo = __floats2half2_rn(dv * x[3*i],   dv * x[3*i+1]);
        __half2 hi = __floats2half2_rn(dv * x[3*i+2], 0.0f);
        uint2 w;
        w.x = *reinterpret_cast<unsigned*>(&lo);
        w.y = *reinterpret_cast<unsigned*>(&hi);
        g_s0[i] = w;
    }
}

// fill CSR + housekeeping tail: zero deg (for next replay's hist), zero pool
// (consumed later this call), zero dummy feature rows (consumed later).
__global__ void fill_kernel(const int* __restrict__ row, const int* __restrict__ col,
                            int e, int n, int pooltot) {
    int i = blockIdx.x * blockDim.x + threadIdx.x;
    int e2 = e >> 1;
    if (i < e2) {
        int2 c = reinterpret_cast<const int2*>(col)[i];
        int2 w = reinterpret_cast<const int2*>(row)[i];
        g_src[atomicAdd(&g_cursor[c.x], 1)] = w.x;
        g_src[atomicAdd(&g_cursor[c.y], 1)] = w.y;
    }
    if (i == 0 && (e & 1))
        g_src[atomicAdd(&g_cursor[col[e - 1]], 1)] = row[e - 1];
    // ---- housekeeping (deg is dead after scan_add_dinv) ----
    if (i < n) g_deg[i] = 0;
    if (i < pooltot) g_pool[i] = 0.0f;    // relu outputs >= 0 -> 0 is max-identity
    if (i < 8) {
        uint4 z; z.x = z.y = z.z = z.w = 0u;
        if (i == 0) { uint2 z2; z2.x = z2.y = 0u; g_s0[n] = z2; }
        if (i < 2)  g_fA[n * 2 + i] = z;    // fA as CIN=16 input (stride 2)
        g_fA[n * 8 + i] = z;                // fA as CIN=48 input (stride 8)
        if (i < 4)  g_fB[n * 4 + i] = z;    // fB as CIN=32 input (stride 4)
    }
}

// ------------------------------- GCN layers -------------------------------

// Layer 1 (Cin=3 pad 4 -> Cout=16): edge pairs, pairwise hadd2 + fp32 acc.
__global__ void layer1_kernel(const float* __restrict__ W, const float* __restrict__ b, int n) {
    __shared__ float Ws[48];
    __shared__ float bs[16];
    if (threadIdx.x < 48) Ws[threadIdx.x] = W[threadIdx.x];
    if (threadIdx.x < 16) bs[threadIdx.x] = b[threadIdx.x];
    __syncthreads();
    int warp = threadIdx.x >> 5, lane = threadIdx.x & 31;
    int v = blockIdx.x * 8 + warp;
    if (v >= n) return;
    const int jbase = g_off[v];
    const int jend  = g_off[v + 1];
    unsigned long long A0 = 0ull, A1 = 0ull;
#pragma unroll 2
    for (int base = jbase + lane * 2; base < jend; base += 64) {
        int2 p = *reinterpret_cast<const int2*>(g_src + base);
        uint2 w0 = g_s0[p.x];
        uint2 w1 = g_s0[p.y];
        acc_h2(A0, __hadd2(u2h(w0.x), u2h(w1.x)));
        acc_h2(A1, __hadd2(u2h(w0.y), u2h(w1.y)));
    }
    float ax, ay, az, azw;
    unpack2(A0, ax, ay);
    unpack2(A1, az, azw);
#pragma unroll
    for (int o = 16; o; o >>= 1) {
        ax += __shfl_xor_sync(0xffffffffu, ax, o);
        ay += __shfl_xor_sync(0xffffffffu, ay, o);
        az += __shfl_xor_sync(0xffffffffu, az, o);
    }
    float dv = g_dinv[v];
    ax *= dv; ay *= dv; az *= dv;
    if (lane < 16) {
        float r = bs[lane] + ax * Ws[lane*3] + ay * Ws[lane*3+1] + az * Ws[lane*3+2];
        __half* outh = reinterpret_cast<__half*>(g_fA);
        outh[v * 16 + lane] = __float2half_rn(dv * fmaxf(r, 0.0f));  // pre-scale
    }
}

// Layers 2-4: uint4 gathers in edge pairs, pairwise hadd2 pre-accumulate,
// float4-vectorized smem matmul.
template <int CIN, int COUT, int IS4, int OS, bool SCALE>
__global__ void layer_kernel(const uint4* __restrict__ s, __half* __restrict__ outh,
                             const float* __restrict__ W, const float* __restrict__ b,
                             int n) {
    constexpr int QC  = CIN / 8;          // 2, 4, 6
    constexpr int EG  = 32 / QC;          // 16, 8, 5
    constexpr int ACT = QC * EG;          // 32, 32, 30
    constexpr int K4  = CIN / 4;          // float4 k-steps
    constexpr int WR  = CIN + 4;          // padded W row; WR/4 odd -> conflict-free
    __shared__ __align__(16) float Wcol[COUT * WR];   // channel-major weights
    __shared__ float bs[COUT];
    __shared__ float4 aggS4[8][K4];
    for (int i = threadIdx.x; i < CIN * COUT; i += blockDim.x) {
        int c = i / CIN, k = i - c * CIN;
        Wcol[c * WR + k] = W[i];
    }
    if (threadIdx.x < COUT) bs[threadIdx.x] = b[threadIdx.x];
    __syncthreads();
    int warp = threadIdx.x >> 5, lane = threadIdx.x & 31;
    int v = blockIdx.x * 8 + warp;
    if (v >= n) return;
    const float dv = g_dinv[v];
    const int eg = lane / QC;
    const int q  = lane - eg * QC;
    const bool active = (ACT == 32) || (lane < ACT);

    const int jbase = g_off[v];
    const int jend  = g_off[v + 1];

    unsigned long long A0 = 0ull, A1 = 0ull, A2 = 0ull, A3 = 0ull;
#pragma unroll 2
    for (int base = active ? (jbase + eg * 2) : jend; base < jend; base += 2 * EG) {
        int2 p = *reinterpret_cast<const int2*>(g_src + base);
        uint4 w0 = s[p.x * IS4 + q];
        uint4 w1 = s[p.y * IS4 + q];
        acc_h2(A0, __hadd2(u2h(w0.x), u2h(w1.x)));   // one fp16 add per element,
        acc_h2(A1, __hadd2(u2h(w0.y), u2h(w1.y)));   // then exact fp32 accumulate
        acc_h2(A2, __hadd2(u2h(w0.z), u2h(w1.z)));
        acc_h2(A3, __hadd2(u2h(w0.w), u2h(w1.w)));
    }
    float f[8];
    unpack2(A0, f[0], f[1]);
    unpack2(A1, f[2], f[3]);
    unpack2(A2, f[4], f[5]);
    unpack2(A3, f[6], f[7]);
    // reduce across edge groups (fp32, exact lane bookkeeping)
    if constexpr (QC == 2 || QC == 4) {
#pragma unroll
        for (int o = QC; o < 32; o <<= 1)
#pragma unroll
            for (int j = 0; j < 8; j++) f[j] += __shfl_xor_sync(0xffffffffu, f[j], o);
    } else {   // QC == 6: groups at lanes q + {0,6,12,18,24}; guarded 3-step sum
#pragma unroll
        for (int j = 0; j < 8; j++) {
            float t = __shfl_down_sync(0xffffffffu, f[j], 18);
            if (lane < 12) f[j] += t;           // q += q+18 ; q+6 += q+24
        }
#pragma unroll
        for (int j = 0; j < 8; j++) {
            float t = __shfl_down_sync(0xffffffffu, f[j], 6);
            if (lane < 6) f[j] += t;            // q += (q+6 + q+24)
        }
#pragma unroll
        for (int j = 0; j < 8; j++) {
            float t = __shfl_down_sync(0xffffffffu, f[j], 12);
            if (lane < 6) f[j] += t;            // q += q+12
        }
    }
    if (lane < QC) {   // two STS.128 per reducing lane
        aggS4[warp][lane * 2]     = make_float4(f[0]*dv, f[1]*dv, f[2]*dv, f[3]*dv);
        aggS4[warp][lane * 2 + 1] = make_float4(f[4]*dv, f[5]*dv, f[6]*dv, f[7]*dv);
    }
    __syncwarp();
    float r0 = bs[lane];
    float r1 = (COUT > 32 && lane + 32 < COUT) ? bs[lane + 32] : 0.0f;
    const float4* w4a = reinterpret_cast<const float4*>(&Wcol[lane * WR]);
    const float4* w4b = (COUT > 32 && lane + 32 < COUT)
                        ? reinterpret_cast<const float4*>(&Wcol[(lane + 32) * WR]) : w4a;
#pragma unroll
    for (int k4 = 0; k4 < K4; k4++) {
        float4 a  = aggS4[warp][k4];       // LDS.128 broadcast
        float4 wa = w4a[k4];               // LDS.128, conflict-free (WR/4 odd)
        r0 += a.x * wa.x + a.y * wa.y + a.z * wa.z + a.w * wa.w;
        if (COUT > 32 && lane + 32 < COUT) {
            float4 wb = w4b[k4];
            r1 += a.x * wb.x + a.y * wb.y + a.z * wb.z + a.w * wb.w;
        }
    }
    r0 = fmaxf(r0, 0.0f);
    if (SCALE) r0 *= dv;
    outh[v * OS + lane] = __float2half_rn(r0);
    if (COUT > 32 && lane + 32 < COUT) {
        r1 = fmaxf(r1, 0.0f);
        if (SCALE) r1 *= dv;
        outh[v * OS + lane + 32] = __float2half_rn(r1);
    }
}

// --------------------------- pool + final MLP ------------------------------

__device__ __forceinline__ void pool_flush(int cur, int c, __half2 m) {
    float2 f = __half22float2(m);
    atomicMax((int*)&g_pool[cur * 64 + 2 * c],     __float_as_int(f.x));
    atomicMax((int*)&g_pool[cur * 64 + 2 * c + 1], __float_as_int(f.y));
}

// 8 warps/block, each warp owns a 64-node chunk (lane = half2 channel pair).
__global__ void pool_kernel(const __half2* __restrict__ h2, const int* __restrict__ batch, int n) {
    const int NPW = 64;
    int warp = threadIdx.x >> 5;
    int c = threadIdx.x & 31;
    int start = blockIdx.x * (8 * NPW) + warp * NPW;
    if (start >= n) return;
    int end = start + NPW; if (end > n) end = n;
    int cur = batch[start];
    __half2 m = __float2half2_rn(0.0f);
    for (int v = start; v < end; v++) {
        int gi = batch[v];
        if (gi != cur) {
            pool_flush(cur, c, m);
            cur = gi;
            m = __float2half2_rn(0.0f);
        }
        m = __hmax2(m, h2[v * 32 + c]);
    }
    pool_flush(cur, c, m);
}

__global__ void mlp_kernel(const float* __restrict__ L1w, const float* __restrict__ L1b,
                           const float* __restrict__ L2w, const float* __restrict__ L2b,
                           float* __restrict__ out) {
    __shared__ float gs[64];
    __shared__ float t1[64];
    int gi = blockIdx.x;
    int t = threadIdx.x;   // 64 threads
    gs[t] = g_pool[gi * 64 + t];
    __syncthreads();
    float acc = L1b[t];
#pragma unroll
    for (int k = 0; k < 64; k++) acc += gs[k] * L1w[t * 64 + k];
    t1[t] = fmaxf(acc, 0.0f);
    __syncthreads();
    if (t < 10) {
        float a = L2b[t];
#pragma unroll
        for (int k = 0; k < 64; k++) a += t1[k] * L2w[t * 64 + k];
        out[gi * 10 + t] = a;
    }
}

// ------------------------------- launcher ----------------------------------

extern "C" void kernel_launch(void* const* d_in, const int* in_sizes, int n_in,
                              void* d_out, int out_size) {
    const float* x     = (const float*)d_in[0];
    const int*   ei    = (const int*)d_in[1];
    const int*   batch = (const int*)d_in[2];
    const float* W1 = (const float*)d_in[4];
    const float* b1 = (const float*)d_in[5];
    const float* W2 = (const float*)d_in[6];
    const float* b2 = (const float*)d_in[7];
    const float* W3 = (const float*)d_in[8];
    const float* b3 = (const float*)d_in[9];
    const float* W4 = (const float*)d_in[10];
    const float* b4 = (const float*)d_in[11];
    const float* L1w = (const float*)d_in[12];
    const float* L1b = (const float*)d_in[13];
    const float* L2w = (const float*)d_in[14];
    const float* L2b = (const float*)d_in[15];
    float* out = (float*)d_out;

    const int n = in_sizes[0] / 3;
    const int e = in_sizes[1] / 2;
    const int G = out_size / 10;

    const int* row = ei;
    const int* col = ei + e;

    uint4* fA; cudaGetSymbolAddress((void**)&fA, g_fA);
    uint4* fB; cudaGetSymbolAddress((void**)&fB, g_fB);

    // ---- CSR build + prep (deg/pool/dummies pre-zeroed by previous call's
    //      fill tail; first call relies on static zero-init) ----
    {
        hist_kernel<<<((e >> 1) + 255) / 256, 256>>>(col, e);
        int nblk = (n + 511) / 512;
        scan_local<<<nblk, 256>>>(n);
        scan_add_dinv<<<(n + 255) / 256, 256>>>(x, n, nblk);
        fill_kernel<<<((e >> 1) + 255) / 256, 256>>>(row, col, e, n, G * 64);
    }

    const int agg_grid = (n + 7) / 8;   // 8 warps/block, warp per node

    // ---- fused layers: gather(Cin, fp16) -> W -> relu -> (dinv-prescale) ----
    layer1_kernel<<<agg_grid, 256>>>(W1, b1, n);                                  // 3->16 -> fA (stride 2)
    layer_kernel<16, 32, 2, 32, true ><<<agg_grid, 256>>>(fA, (__half*)fB, W2, b2, n); // 16->32 -> fB (stride 4)
    layer_kernel<32, 48, 4, 64, true ><<<agg_grid, 256>>>(fB, (__half*)fA, W3, b3, n); // 32->48 -> fA (stride 8)
    layer_kernel<48, 64, 8, 64, false><<<agg_grid, 256>>>(fA, (__half*)fB, W4, b4, n); // 48->64 -> fB

    // ---- pool + MLP ----
    pool_kernel<<<(n + 511) / 512, 256>>>((const __half2*)fB, batch, n);
    mlp_kernel<<<G, 64>>>(L1w, L1b, L2w, L2b, out);
}

// round 17
// speedup vs baseline: 1.2031x; 1.0124x over previous
#include <cuda_runtime.h>
#include <cuda_fp16.h>
#include <cuda_bf16.h>

// ---------------------------------------------------------------------------
// GNN: 4x GCNConv (3->16->32->48->64, relu) + global max pool + 2-layer MLP
// Round-17 (resubmit of r16 after infra failure): atomic-free fill via edge
// ranks. hist's atomicAdd return value IS the rank -> store it; fill becomes
// pure gather+scatter (pos = off+1+rank). g_cursor eliminated.
// ---------------------------------------------------------------------------

#define N_MAX 131072
#define E_MAX 3500000
#define G_MAX 512

__device__ int    g_deg[N_MAX];            // real in-degree; zeroed by fill tail
__device__ int    g_rank[E_MAX];           // per-edge rank among same-col edges
__device__ int    g_off[N_MAX + 1];        // padded CSR offsets (all even)
__device__ __align__(16) int g_src[E_MAX]; // CSR: [self, real edges..., pad(n)]
__device__ int    g_bsum[256];
__device__ float  g_dinv[N_MAX];
__device__ uint2  g_s0[N_MAX + 1];          // layer-1 input half4, dinv-scaled (+dummy)
__device__ uint4  g_fA[(N_MAX + 1) * 8];    // feature buffer A
__device__ uint4  g_fB[(N_MAX + 1) * 8];    // feature buffer B
__device__ float  g_pool[G_MAX * 64];       // zeroed by fill tail

// packed f32x2 accumulate of a half2 word: acc(2xf32) += cvt(2xf16)
__device__ __forceinline__ void acc_h2(unsigned long long& acc, __half2 h) {
    unsigned h2v = *reinterpret_cast<unsigned*>(&h);
    asm("{\n\t"
        ".reg .b16 h0, h1;\n\t"
        ".reg .f32 f0, f1;\n\t"
        ".reg .b64 t;\n\t"
        "mov.b32 {h0, h1}, %1;\n\t"
        "cvt.f32.f16 f0, h0;\n\t"
        "cvt.f32.f16 f1, h1;\n\t"
        "mov.b64 t, {f0, f1};\n\t"
        "add.rn.f32x2 %0, %0, t;\n\t"
        "}" : "+l"(acc) : "r"(h2v));
}
__device__ __forceinline__ void unpack2(unsigned long long a, float& lo, float& hi) {
    asm("mov.b64 {%0, %1}, %2;" : "=f"(lo), "=f"(hi) : "l"(a));
}
__device__ __forceinline__ __half2 u2h(unsigned u) { return *reinterpret_cast<__half2*>(&u); }

// ---------------------------- CSR construction ----------------------------
// NOTE: g_deg and g_pool must be ZERO at entry of each kernel_launch call.
// First call: CUDA zero-initializes __device__ globals. Subsequent calls:
// fill_kernel's tail re-zeroes them (it runs after their last consumer).

// histogram + per-edge rank (the atomicAdd return value)
__global__ void hist_kernel(const int* __restrict__ col, int e) {
    int i = blockIdx.x * blockDim.x + threadIdx.x;
    int e2 = e >> 1;
    if (i < e2) {
        int2 c = reinterpret_cast<const int2*>(col)[i];
        int r0 = atomicAdd(&g_deg[c.x], 1);
        int r1 = atomicAdd(&g_deg[c.y], 1);
        reinterpret_cast<int2*>(g_rank)[i] = make_int2(r0, r1);
    }
    if (i == 0 && (e & 1))
        g_rank[e - 1] = atomicAdd(&g_deg[col[e - 1]], 1);
}

// padded per-node slot count: self + real edges, rounded up to even
__device__ __forceinline__ int padded_cnt(int deg) { return (deg + 2) & ~1; }

// block-local exclusive scan of padded counts -> g_off (local) + g_bsum
__global__ void scan_local(int n) {
    __shared__ int sm[256];
    int b = blockIdx.x, t = threadIdx.x;
    int i0 = b * 512 + 2 * t, i1 = i0 + 1;
    int v0 = (i0 < n) ? padded_cnt(g_deg[i0]) : 0;
    int v1 = (i1 < n) ? padded_cnt(g_deg[i1]) : 0;
    sm[t] = v0 + v1;
    __syncthreads();
    for (int o = 1; o < 256; o <<= 1) {
        int x = (t >= o) ? sm[t - o] : 0;
        __syncthreads();
        sm[t] += x;
        __syncthreads();
    }
    int ex = (t > 0) ? sm[t - 1] : 0;
    if (i0 < n) g_off[i0] = ex;
    if (i1 < n) g_off[i1] = ex + v0;
    if (t == 255) g_bsum[b] = sm[255];
}

// finalize offsets (each block re-scans the spine itself); self-loop entry +
// pad entry; dinv + s0 prep.
__global__ void scan_add_dinv(const float* __restrict__ x, int n, int nblk) {
    __shared__ int sp[256];
    int t = threadIdx.x;
    sp[t] = (t < nblk) ? g_bsum[t] : 0;
    __syncthreads();
    for (int o = 1; o < 256; o <<= 1) {
        int v = (t >= o) ? sp[t - o] : 0;
        __syncthreads();
        sp[t] += v;
        __syncthreads();
    }
    int i = blockIdx.x * blockDim.x + t;
    if (i < n) {
        int chunk = i >> 9;
        int off = g_off[i] + ((chunk > 0) ? sp[chunk - 1] : 0);
        g_off[i] = off;
        g_src[off] = i;                   // slot 0 = self loop
        int dp1 = g_deg[i] + 1;           // self + real edges
        if (dp1 & 1) g_src[off + dp1] = n;   // pad to even with dummy
        if (i == n - 1) g_off[n] = off + ((dp1 + 1) & ~1);
        float dv = rsqrtf((float)dp1);
        g_dinv[i] = dv;
        __half2 lo = __floats2half2_rn(dv * x[3*i],   dv * x[3*i+1]);
        __half2 hi = __floats2half2_rn(dv * x[3*i+2], 0.0f);
        uint2 w;
        w.x = *reinterpret_cast<unsigned*>(&lo);
        w.y = *reinterpret_cast<unsigned*>(&hi);
        g_s0[i] = w;
    }
}

// ATOMIC-FREE fill: pos = off[col] + 1 + rank. Plus housekeeping tail:
// zero deg (for next replay's hist), zero pool, zero dummy feature rows.
__global__ void fill_kernel(const int* __restrict__ row, const int* __restrict__ col,
                            int e, int n, int pooltot) {
    int i = blockIdx.x * blockDim.x + threadIdx.x;
    int e2 = e >> 1;
    if (i < e2) {
        int2 c = reinterpret_cast<const int2*>(col)[i];
        int2 r = reinterpret_cast<const int2*>(g_rank)[i];
        int2 w = reinterpret_cast<const int2*>(row)[i];
        g_src[g_off[c.x] + 1 + r.x] = w.x;
        g_src[g_off[c.y] + 1 + r.y] = w.y;
    }
    if (i == 0 && (e & 1))
        g_src[g_off[col[e - 1]] + 1 + g_rank[e - 1]] = row[e - 1];
    // ---- housekeeping (deg is dead after scan_add_dinv) ----
    if (i < n) g_deg[i] = 0;
    if (i < pooltot) g_pool[i] = 0.0f;    // relu outputs >= 0 -> 0 is max-identity
    if (i < 8) {
        uint4 z; z.x = z.y = z.z = z.w = 0u;
        if (i == 0) { uint2 z2; z2.x = z2.y = 0u; g_s0[n] = z2; }
        if (i < 2)  g_fA[n * 2 + i] = z;    // fA as CIN=16 input (stride 2)
        g_fA[n * 8 + i] = z;                // fA as CIN=48 input (stride 8)
        if (i < 4)  g_fB[n * 4 + i] = z;    // fB as CIN=32 input (stride 4)
    }
}

// ------------------------------- GCN layers -------------------------------

// Layer 1 (Cin=3 pad 4 -> Cout=16): edge pairs, pairwise hadd2 + fp32 acc.
__global__ void layer1_kernel(const float* __restrict__ W, const float* __restrict__ b, int n) {
    __shared__ float Ws[48];
    __shared__ float bs[16];
    if (threadIdx.x < 48) Ws[threadIdx.x] = W[threadIdx.x];
    if (threadIdx.x < 16) bs[threadIdx.x] = b[threadIdx.x];
    __syncthreads();
    int warp = threadIdx.x >> 5, lane = threadIdx.x & 31;
    int v = blockIdx.x * 8 + warp;
    if (v >= n) return;
    const int jbase = g_off[v];
    const int jend  = g_off[v + 1];
    unsigned long long A0 = 0ull, A1 = 0ull;
#pragma unroll 2
    for (int base = jbase + lane * 2; base < jend; base += 64) {
        int2 p = *reinterpret_cast<const int2*>(g_src + base);
        uint2 w0 = g_s0[p.x];
        uint2 w1 = g_s0[p.y];
        acc_h2(A0, __hadd2(u2h(w0.x), u2h(w1.x)));
        acc_h2(A1, __hadd2(u2h(w0.y), u2h(w1.y)));
    }
    float ax, ay, az, azw;
    unpack2(A0, ax, ay);
    unpack2(A1, az, azw);
#pragma unroll
    for (int o = 16; o; o >>= 1) {
        ax += __shfl_xor_sync(0xffffffffu, ax, o);
        ay += __shfl_xor_sync(0xffffffffu, ay, o);
        az += __shfl_xor_sync(0xffffffffu, az, o);
    }
    float dv = g_dinv[v];
    ax *= dv; ay *= dv; az *= dv;
    if (lane < 16) {
        float r = bs[lane] + ax * Ws[lane*3] + ay * Ws[lane*3+1] + az * Ws[lane*3+2];
        __half* outh = reinterpret_cast<__half*>(g_fA);
        outh[v * 16 + lane] = __float2half_rn(dv * fmaxf(r, 0.0f));  // pre-scale
    }
}

// Layers 2-4: uint4 gathers in edge pairs, pairwise hadd2 pre-accumulate,
// float4-vectorized smem matmul.
template <int CIN, int COUT, int IS4, int OS, bool SCALE>
__global__ void layer_kernel(const uint4* __restrict__ s, __half* __restrict__ outh,
                             const float* __restrict__ W, const float* __restrict__ b,
                             int n) {
    constexpr int QC  = CIN / 8;          // 2, 4, 6
    constexpr int EG  = 32 / QC;          // 16, 8, 5
    constexpr int ACT = QC * EG;          // 32, 32, 30
    constexpr int K4  = CIN / 4;          // float4 k-steps
    constexpr int WR  = CIN + 4;          // padded W row; WR/4 odd -> conflict-free
    __shared__ __align__(16) float Wcol[COUT * WR];   // channel-major weights
    __shared__ float bs[COUT];
    __shared__ float4 aggS4[8][K4];
    for (int i = threadIdx.x; i < CIN * COUT; i += blockDim.x) {
        int c = i / CIN, k = i - c * CIN;
        Wcol[c * WR + k] = W[i];
    }
    if (threadIdx.x < COUT) bs[threadIdx.x] = b[threadIdx.x];
    __syncthreads();
    int warp = threadIdx.x >> 5, lane = threadIdx.x & 31;
    int v = blockIdx.x * 8 + warp;
    if (v >= n) return;
    const float dv = g_dinv[v];
    const int eg = lane / QC;
    const int q  = lane - eg * QC;
    const bool active = (ACT == 32) || (lane < ACT);

    const int jbase = g_off[v];
    const int jend  = g_off[v + 1];

    unsigned long long A0 = 0ull, A1 = 0ull, A2 = 0ull, A3 = 0ull;
#pragma unroll 2
    for (int base = active ? (jbase + eg * 2) : jend; base < jend; base += 2 * EG) {
        int2 p = *reinterpret_cast<const int2*>(g_src + base);
        uint4 w0 = s[p.x * IS4 + q];
        uint4 w1 = s[p.y * IS4 + q];
        acc_h2(A0, __hadd2(u2h(w0.x), u2h(w1.x)));   // one fp16 add per element,
        acc_h2(A1, __hadd2(u2h(w0.y), u2h(w1.y)));   // then exact fp32 accumulate
        acc_h2(A2, __hadd2(u2h(w0.z), u2h(w1.z)));
        acc_h2(A3, __hadd2(u2h(w0.w), u2h(w1.w)));
    }
    float f[8];
    unpack2(A0, f[0], f[1]);
    unpack2(A1, f[2], f[3]);
    unpack2(A2, f[4], f[5]);
    unpack2(A3, f[6], f[7]);
    // reduce across edge groups (fp32, exact lane bookkeeping)
    if constexpr (QC == 2 || QC == 4) {
#pragma unroll
        for (int o = QC; o < 32; o <<= 1)
#pragma unroll
            for (int j = 0; j < 8; j++) f[j] += __shfl_xor_sync(0xffffffffu, f[j], o);
    } else {   // QC == 6: groups at lanes q + {0,6,12,18,24}; guarded 3-step sum
#pragma unroll
        for (int j = 0; j < 8; j++) {
            float t = __shfl_down_sync(0xffffffffu, f[j], 18);
            if (lane < 12) f[j] += t;           // q += q+18 ; q+6 += q+24
        }
#pragma unroll
        for (int j = 0; j < 8; j++) {
            float t = __shfl_down_sync(0xffffffffu, f[j], 6);
            if (lane < 6) f[j] += t;            // q += (q+6 + q+24)
        }
#pragma unroll
        for (int j = 0; j < 8; j++) {
            float t = __shfl_down_sync(0xffffffffu, f[j], 12);
            if (lane < 6) f[j] += t;            // q += q+12
        }
    }
    if (lane < QC) {   // two STS.128 per reducing lane
        aggS4[warp][lane * 2]     = make_float4(f[0]*dv, f[1]*dv, f[2]*dv, f[3]*dv);
        aggS4[warp][lane * 2 + 1] = make_float4(f[4]*dv, f[5]*dv, f[6]*dv, f[7]*dv);
    }
    __syncwarp();
    float r0 = bs[lane];
    float r1 = (COUT > 32 && lane + 32 < COUT) ? bs[lane + 32] : 0.0f;
    const float4* w4a = reinterpret_cast<const float4*>(&Wcol[lane * WR]);
    const float4* w4b = (COUT > 32 && lane + 32 < COUT)
                        ? reinterpret_cast<const float4*>(&Wcol[(lane + 32) * WR]) : w4a;
#pragma unroll
    for (int k4 = 0; k4 < K4; k4++) {
        float4 a  = aggS4[warp][k4];       // LDS.128 broadcast
        float4 wa = w4a[k4];               // LDS.128, conflict-free (WR/4 odd)
        r0 += a.x * wa.x + a.y * wa.y + a.z * wa.z + a.w * wa.w;
        if (COUT > 32 && lane + 32 < COUT) {
            float4 wb = w4b[k4];
            r1 += a.x * wb.x + a.y * wb.y + a.z * wb.z + a.w * wb.w;
        }
    }
    r0 = fmaxf(r0, 0.0f);
    if (SCALE) r0 *= dv;
    outh[v * OS + lane] = __float2half_rn(r0);
    if (COUT > 32 && lane + 32 < COUT) {
        r1 = fmaxf(r1, 0.0f);
        if (SCALE) r1 *= dv;
        outh[v * OS + lane + 32] = __float2half_rn(r1);
    }
}

// --------------------------- pool + final MLP ------------------------------

__device__ __forceinline__ void pool_flush(int cur, int c, __half2 m) {
    float2 f = __half22float2(m);
    atomicMax((int*)&g_pool[cur * 64 + 2 * c],     __float_as_int(f.x));
    atomicMax((int*)&g_pool[cur * 64 + 2 * c + 1], __float_as_int(f.y));
}

// 8 warps/block, each warp owns a 64-node chunk (lane = half2 channel pair).
__global__ void pool_kernel(const __half2* __restrict__ h2, const int* __restrict__ batch, int n) {
    const int NPW = 64;
    int warp = threadIdx.x >> 5;
    int c = threadIdx.x & 31;
    int start = blockIdx.x * (8 * NPW) + warp * NPW;
    if (start >= n) return;
    int end = start + NPW; if (end > n) end = n;
    int cur = batch[start];
    __half2 m = __float2half2_rn(0.0f);
    for (int v = start; v < end; v++) {
        int gi = batch[v];
        if (gi != cur) {
            pool_flush(cur, c, m);
            cur = gi;
            m = __float2half2_rn(0.0f);
        }
        m = __hmax2(m, h2[v * 32 + c]);
    }
    pool_flush(cur, c, m);
}

__global__ void mlp_kernel(const float* __restrict__ L1w, const float* __restrict__ L1b,
                           const float* __restrict__ L2w, const float* __restrict__ L2b,
                           float* __restrict__ out) {
    __shared__ float gs[64];
    __shared__ float t1[64];
    int gi = blockIdx.x;
    int t = threadIdx.x;   // 64 threads
    gs[t] = g_pool[gi * 64 + t];
    __syncthreads();
    float acc = L1b[t];
#pragma unroll
    for (int k = 0; k < 64; k++) acc += gs[k] * L1w[t * 64 + k];
    t1[t] = fmaxf(acc, 0.0f);
    __syncthreads();
    if (t < 10) {
        float a = L2b[t];
#pragma unroll
        for (int k = 0; k < 64; k++) a += t1[k] * L2w[t * 64 + k];
        out[gi * 10 + t] = a;
    }
}

// ------------------------------- launcher ----------------------------------

extern "C" void kernel_launch(void* const* d_in, const int* in_sizes, int n_in,
                              void* d_out, int out_size) {
    const float* x     = (const float*)d_in[0];
    const int*   ei    = (const int*)d_in[1];
    const int*   batch = (const int*)d_in[2];
    const float* W1 = (const float*)d_in[4];
    const float* b1 = (const float*)d_in[5];
    const float* W2 = (const float*)d_in[6];
    const float* b2 = (const float*)d_in[7];
    const float* W3 = (const float*)d_in[8];
    const float* b3 = (const float*)d_in[9];
    const float* W4 = (const float*)d_in[10];
    const float* b4 = (const float*)d_in[11];
    const float* L1w = (const float*)d_in[12];
    const float* L1b = (const float*)d_in[13];
    const float* L2w = (const float*)d_in[14];
    const float* L2b = (const float*)d_in[15];
    float* out = (float*)d_out;

    const int n = in_sizes[0] / 3;
    const int e = in_sizes[1] / 2;
    const int G = out_size / 10;

    const int* row = ei;
    const int* col = ei + e;

    uint4* fA; cudaGetSymbolAddress((void**)&fA, g_fA);
    uint4* fB; cudaGetSymbolAddress((void**)&fB, g_fB);

    // ---- CSR build + prep (deg/pool/dummies pre-zeroed by previous call's
    //      fill tail; first call relies on static zero-init) ----
    {
        hist_kernel<<<((e >> 1) + 255) / 256, 256>>>(col, e);
        int nblk = (n + 511) / 512;
        scan_local<<<nblk, 256>>>(n);
        scan_add_dinv<<<(n + 255) / 256, 256>>>(x, n, nblk);
        fill_kernel<<<((e >> 1) + 255) / 256, 256>>>(row, col, e, n, G * 64);
    }

    const int agg_grid = (n + 7) / 8;   // 8 warps/block, warp per node

    // ---- fused layers: gather(Cin, fp16) -> W -> relu -> (dinv-prescale) ----
    layer1_kernel<<<agg_grid, 256>>>(W1, b1, n);                                  // 3->16 -> fA (stride 2)
    layer_kernel<16, 32, 2, 32, true ><<<agg_grid, 256>>>(fA, (__half*)fB, W2, b2, n); // 16->32 -> fB (stride 4)
    layer_kernel<32, 48, 4, 64, true ><<<agg_grid, 256>>>(fB, (__half*)fA, W3, b3, n); // 32->48 -> fA (stride 8)
    layer_kernel<48, 64, 8, 64, false><<<agg_grid, 256>>>(fA, (__half*)fB, W4, b4, n); // 48->64 -> fB

    // ---- pool + MLP ----
    pool_kernel<<<(n + 511) / 512, 256>>>((const __half2*)fB, batch, n);
    mlp_kernel<<<G, 64>>>(L1w, L1b, L2w, L2b, out);
}